// round 14
// baseline (speedup 1.0000x reference)
#include <cuda_runtime.h>
#include <cstdint>

// ---------------------------------------------------------------------------
// LocationSlayerArch, round 14: R8 arithmetic (frozen order), gemm h-block
// halved to 64 (40KB weight tile -> 4 blocks/SM -> 64 warps/SM latency
// hiding). Per-h accumulation remains single-accumulator ascending-c.
// ---------------------------------------------------------------------------

#define N_BATCH 128
#define T_SEQ   156
#define C_IN    156
#define H_DIM   1024
#define O_DIM   20
#define HB_CNT  8                     // 128-h blocks (neuron/final layout)
#define HBG_CNT 16                    // 64-h gemm blocks
#define HW      64                    // h per gemm block
#define HB_SZ   128
#define IDX_CAP 160
#define ROW_BYTES 256                 // ws row stride (64 floats)
#define ZROW_OFF ((unsigned)(C_IN * ROW_BYTES))
#define CHUNK_T 78                    // 156 = 2 * 78
#define NCHUNK  2
#define NGRP    8                     // batch samples per gemm block

#define LAM_S  0.90483741803595952f
#define K_PSP  0.27182818284590452f
#define LAM_R  0.36787944117144233f
#define C_REF  -54.365636569180902f
#define C_P16  1.1253517471925912e-07f
#define C_Q16  1.8005627955081459e-06f
#define THETA  10.0f

__device__ __constant__ int c_td[39] = {
    11,25,35,4,18,30,7,2,20,37,29,12,9,33,23,16,1,6,15,21,
    27,34,39,24,17,10,31,38,28,14,3,22,32,8,19,36,5,13,26};

#define NSLAB (2 * N_BATCH * HB_CNT)           // 2048 128-h slabs
#define NSLABG (2 * N_BATCH * HBG_CNT)         // 4096 64-h slabs
__device__ unsigned g_idx[(size_t)2 * N_BATCH * T_SEQ * IDX_CAP];   // 25.6MB
__device__ int      g_cnt[2 * N_BATCH * T_SEQ];
__device__ float    g_w1t[2][C_IN * H_DIM];                         // 1.3MB
__device__ float    g_prechunk[(size_t)NSLABG * CHUNK_T * HW];      // 81.8MB
__device__ float4   g_stF[NSLAB * HB_SZ];
__device__ unsigned g_stH[NSLAB * HB_SZ];
__device__ unsigned g_sb[(size_t)NSLAB * T_SEQ * 4];                // 5.1MB

#define LDS64(a, addr) \
    asm volatile("ld.shared.b64 %0, [%1];" : "=l"(a) : "r"(addr))
#define LDSV2(a, b, addr) \
    asm volatile("ld.shared.v2.b64 {%0,%1}, [%2];" : "=l"(a), "=l"(b) : "r"(addr))
#define FADD2(acc, x) \
    asm("add.rn.f32x2 %0, %0, %1;" : "+l"(acc) : "l"(x))

// ---------------------------------------------------------------------------
// K-1: transpose layer-1 weights: g_w1t[path][c*1024 + h] = w[h*156 + c].
// ---------------------------------------------------------------------------
__global__ void __launch_bounds__(256) k_wt(const float* __restrict__ w_main,
                                            const float* __restrict__ w_loc) {
    int i = blockIdx.x * 256 + threadIdx.x;
    if (i >= 2 * C_IN * H_DIM) return;
    int path = i / (C_IN * H_DIM);
    int r = i % (C_IN * H_DIM);
    int c = r / H_DIM, h = r % H_DIM;
    const float* w = path ? w_loc : w_main;
    g_w1t[path][r] = w[(size_t)h * C_IN + c];
}

// ---------------------------------------------------------------------------
// K0: ballot-compacted active-index lists (premultiplied by ROW_BYTES=256).
// ---------------------------------------------------------------------------
__global__ void __launch_bounds__(256) k_bitify(const float* __restrict__ x) {
    extern __shared__ float xs[];                 // [C_IN][T_SEQ]
    int n = blockIdx.x;
    const float* xb = x + (size_t)n * C_IN * T_SEQ;
    for (int i = threadIdx.x; i < C_IN * T_SEQ; i += blockDim.x) xs[i] = xb[i];
    __syncthreads();

    int wrp = threadIdx.x >> 5, lane = threadIdx.x & 31;
    for (int task = wrp; task < 2 * T_SEQ; task += 8) {
        int path = task >= T_SEQ;
        int seq = path ? task - T_SEQ : task;
        unsigned* ob = g_idx + ((size_t)(path * N_BATCH + n) * T_SEQ + seq) * IDX_CAP;

        int pc = 0;
        if (path) {
            int blk = seq / 78, j2 = seq % 78;
            pc = 2 * c_td[j2 >> 1] - 2 + (j2 & 1) + blk * 78;   // PERM[seq]
        }
        int total = 0;
        #pragma unroll
        for (int w = 0; w < 5; w++) {
            int j = w * 32 + lane;
            bool bit = false;
            if (j < C_IN)
                bit = (path ? xs[pc * T_SEQ + j] : xs[j * T_SEQ + seq]) > 0.5f;
            unsigned m = __ballot_sync(0xffffffffu, bit);
            int pos = total + __popc(m & ((1u << lane) - 1u));
            if (bit) ob[pos] = (unsigned)(j * ROW_BYTES);
            total += __popc(m);
        }
        if (lane == 0) {
            while (total & 3) ob[total++] = ZROW_OFF;
            g_cnt[(path * N_BATCH + n) * T_SEQ + seq] = total;
        }
    }
}

// ---------------------------------------------------------------------------
// K1a: sparse GEMM1, 64-h blocks. grid (16 hbg, N/8, path) = 512 blocks,
// 512 threads, 40KB smem -> 4 blocks/SM = 64 warps/SM.
// Lane owns 2 h; single f32x2 accumulator per t (ascending-c order, frozen).
// ---------------------------------------------------------------------------
__global__ void __launch_bounds__(512, 4) k_gemm1(int t0) {
    extern __shared__ float ws[];   // [157][64]; row 156 = zeros
    int hbg = blockIdx.x, ng = blockIdx.y, path = blockIdx.z;
    int tid = threadIdx.x;

    const float* wt = g_w1t[path] + hbg * HW;
    for (int i = tid; i < C_IN * HW; i += 512) {
        int c = i >> 6, hl = i & 63;
        ws[i] = wt[c * H_DIM + hl];
    }
    for (int i = tid; i < HW; i += 512) ws[C_IN * HW + i] = 0.0f;
    __syncthreads();

    uint32_t ws32;
    asm("{ .reg .u64 t; cvta.to.shared.u64 t, %1; cvt.u32.u64 %0, t; }"
        : "=r"(ws32) : "l"(ws));

    int wrp = tid >> 5, lane = tid & 31;
    uint32_t base = ws32 + lane * 8;
    int n = ng * NGRP + (wrp >> 1);
    int strip = wrp & 1;
    float* pp = g_prechunk + (size_t)((path * N_BATCH + n) * HBG_CNT + hbg) * (CHUNK_T * HW);
    const int seqbase = (path * N_BATCH + n) * T_SEQ + t0;

    for (int tl = strip; tl < CHUNK_T; tl += 2) {
        const unsigned* ib = g_idx + (size_t)(seqbase + tl) * IDX_CAP;
        int cnt = g_cnt[seqbase + tl];
        unsigned long long acc = 0ULL;
        for (int k = 0; k < cnt; k += 4) {
            uint4 v = *(const uint4*)(ib + k);
            unsigned long long a;
            LDS64(a, base + v.x); FADD2(acc, a);
            LDS64(a, base + v.y); FADD2(acc, a);
            LDS64(a, base + v.z); FADD2(acc, a);
            LDS64(a, base + v.w); FADD2(acc, a);
        }
        *(float2*)(pp + tl * HW + lane * 2) = *reinterpret_cast<float2*>(&acc);
    }
}

// ---------------------------------------------------------------------------
// K1b: layer-1 recurrence for one chunk; spikes -> bitmasks.
// grid (8 j, n, path), 128 threads. Block j covers h = j*128..j*128+127,
// stored as two 64-h gemm slabs (2j, 2j+1). State layout unchanged.
// ---------------------------------------------------------------------------
__global__ void __launch_bounds__(HB_SZ) k_neuron1(int chunk) {
    int j = blockIdx.x, n = blockIdx.y, path = blockIdx.z;
    int tid = threadIdx.x;
    int lane = tid & 31, wrp = tid >> 5;

    int slab8 = (path * N_BATCH + n) * HB_CNT + j;
    int slab16 = (path * N_BATCH + n) * HBG_CNT + 2 * j + (tid >> 6);
    const float* pp = g_prechunk + (size_t)slab16 * (CHUNK_T * HW) + (tid & 63);
    unsigned* sbout = g_sb + (size_t)slab8 * (T_SEQ * 4) + (chunk * CHUNK_T) * 4;

    float A, B, P, Q;
    unsigned hist;
    if (chunk == 0) {
        A = B = P = Q = 0.f; hist = 0u;
    } else {
        float4 st = g_stF[slab8 * HB_SZ + tid];
        A = st.x; B = st.y; P = st.z; Q = st.w;
        hist = g_stH[slab8 * HB_SZ + tid];
    }

    #pragma unroll 6
    for (int tl = 0; tl < CHUNK_T; tl++) {
        float acc = pp[tl * HW];
        B = LAM_S * (B + A);
        A = LAM_S * A + acc;
        float u  = K_PSP * B;
        float um = u + C_REF * Q;
        unsigned spk = (um >= THETA) ? 1u : 0u;
        float s = (float)spk;
        float aged = (float)((hist >> 14) & 1u);
        Q = LAM_R * (Q + P + s) - aged * C_Q16;
        P = LAM_R * (P + s)     - aged * C_P16;
        hist = (hist << 1) | spk;
        unsigned bal = __ballot_sync(0xffffffffu, spk);
        if (lane == 0) sbout[tl * 4 + wrp] = bal;
    }

    if (chunk < NCHUNK - 1) {
        g_stF[slab8 * HB_SZ + tid] = make_float4(A, B, P, Q);
        g_stH[slab8 * HB_SZ + tid] = hist;
    }
}

// ---------------------------------------------------------------------------
// K2: s1 x W2 from bitmasks (per-hb partials summed in ascending hb order),
// then layer-2 recurrence + output. grid 256 = (path, n), 256 threads.
// ---------------------------------------------------------------------------
#define TO (T_SEQ * O_DIM)   // 3120
__global__ void __launch_bounds__(256) k_final(float* __restrict__ out,
                                               const float* __restrict__ wb_main,
                                               const float* __restrict__ wb_loc) {
    extern __shared__ float smem[];
    float* w2s = smem;                   // [1024][20], 80KB
    float* v   = smem + H_DIM * O_DIM;   // [156][20]

    int b = blockIdx.x;
    int path = b >> 7, n = b & 127;
    int tid = threadIdx.x;
    const float* wb = path ? wb_loc : wb_main;

    for (int i = tid; i < H_DIM * O_DIM; i += 256) {
        int o = i / H_DIM, h = i % H_DIM;
        w2s[h * O_DIM + o] = wb[(size_t)o * H_DIM + h];
    }
    __syncthreads();

    uint32_t w2s32;
    asm("{ .reg .u64 t; cvta.to.shared.u64 t, %1; cvt.u32.u64 %0, t; }"
        : "=r"(w2s32) : "l"(w2s));

    const unsigned* sbb = g_sb + (size_t)(path * N_BATCH + n) * HB_CNT * (T_SEQ * 4);

    for (int t = tid; t < T_SEQ; t += 256) {
        unsigned long long acc[10];
        #pragma unroll
        for (int i = 0; i < 10; i++) acc[i] = 0ULL;
        for (int hb = 0; hb < HB_CNT; hb++) {
            unsigned long long tmp[10];
            #pragma unroll
            for (int i = 0; i < 10; i++) tmp[i] = 0ULL;
            const unsigned* sm = sbb + (size_t)hb * (T_SEQ * 4) + t * 4;
            uint32_t hbbase = w2s32 + (unsigned)(hb * HB_SZ * O_DIM * 4);
            #pragma unroll
            for (int wd = 0; wd < 4; wd++) {
                unsigned m = sm[wd];
                while (m) {
                    int j = __ffs(m) - 1;
                    m &= m - 1u;
                    uint32_t row = hbbase + (unsigned)((wd * 32 + j) * (O_DIM * 4));
                    unsigned long long a, c;
                    LDSV2(a, c, row);
                    FADD2(tmp[0], a); FADD2(tmp[1], c);
                    LDSV2(a, c, row + 16);
                    FADD2(tmp[2], a); FADD2(tmp[3], c);
                    LDSV2(a, c, row + 32);
                    FADD2(tmp[4], a); FADD2(tmp[5], c);
                    LDSV2(a, c, row + 48);
                    FADD2(tmp[6], a); FADD2(tmp[7], c);
                    LDSV2(a, c, row + 64);
                    FADD2(tmp[8], a); FADD2(tmp[9], c);
                }
            }
            #pragma unroll
            for (int i = 0; i < 10; i++) FADD2(acc[i], tmp[i]);
        }
        float2* vp = (float2*)(v + t * O_DIM);
        #pragma unroll
        for (int i = 0; i < 10; i++) vp[i] = *reinterpret_cast<float2*>(&acc[i]);
    }
    __syncthreads();

    if (tid < O_DIM) {
        int o = tid;
        float* op = out + ((size_t)n * O_DIM + o) * 312 + path * T_SEQ;
        float A = 0.f, B = 0.f, P = 0.f, Q = 0.f;
        unsigned hist = 0u;
        #pragma unroll 4
        for (int t = 0; t < T_SEQ; t++) {
            float pre = v[t * O_DIM + o];
            B = LAM_S * (B + A);
            A = LAM_S * A + pre;
            float u  = K_PSP * B;
            float um = u + C_REF * Q;
            unsigned spk = (um >= THETA) ? 1u : 0u;
            float s = (float)spk;
            float aged = (float)((hist >> 14) & 1u);
            Q = LAM_R * (Q + P + s) - aged * C_Q16;
            P = LAM_R * (P + s)     - aged * C_P16;
            hist = (hist << 1) | spk;
            op[t] = s;
        }
    }
}

// ---------------------------------------------------------------------------
extern "C" void kernel_launch(void* const* d_in, const int* in_sizes, int n_in,
                              void* d_out, int out_size) {
    const float* x   = (const float*)d_in[0];
    const float* w1  = (const float*)d_in[1];
    const float* w2  = (const float*)d_in[2];
    const float* wl1 = (const float*)d_in[3];
    const float* wl2 = (const float*)d_in[4];
    float* out = (float*)d_out;

    const int SM0 = C_IN * T_SEQ * 4;                    // 97344
    const int SM1 = 157 * HW * 4;                        // 40192
    const int SM2 = (H_DIM * O_DIM + TO) * 4;            // 94400
    cudaFuncSetAttribute(k_bitify, cudaFuncAttributeMaxDynamicSharedMemorySize, SM0);
    cudaFuncSetAttribute(k_gemm1,  cudaFuncAttributeMaxDynamicSharedMemorySize, SM1);
    cudaFuncSetAttribute(k_final,  cudaFuncAttributeMaxDynamicSharedMemorySize, SM2);

    k_wt<<<(2 * C_IN * H_DIM + 255) / 256, 256>>>(w1, wl1);
    k_bitify<<<N_BATCH, 256, SM0>>>(x);

    dim3 gg(HBG_CNT, N_BATCH / NGRP, 2);   // 512 blocks
    dim3 gn(HB_CNT, N_BATCH, 2);
    for (int c = 0; c < NCHUNK; c++) {
        k_gemm1<<<gg, 512, SM1>>>(c * CHUNK_T);
        k_neuron1<<<gn, HB_SZ>>>(c);
    }

    k_final<<<2 * N_BATCH, 256, SM2>>>(out, w2, wl2);
}

// round 15
// speedup vs baseline: 1.4231x; 1.4231x over previous
#include <cuda_runtime.h>
#include <cstdint>

// ---------------------------------------------------------------------------
// LocationSlayerArch, round 15: warp-level fusion. One warp owns the FULL
// (path, n, hb=128h) layer-1 pipeline — sparse matvec (R8-frozen order) +
// psp/refractory recurrence in registers + canonical spike-bit packing —
// with ZERO block-level synchronization in the t-loop. g_prechunk, state
// buffers, and the neuron kernel are deleted.
//   k_wt     : W1/Wl1 -> g_w1t[path][c][h]
//   k_bitify : ballot-compacted active-index lists
//   k_fused  : layer-1 matvec+recurrence per warp -> spike bitmasks g_sb
//   k_final  : s1 x W2 GEMM from bitmasks + layer-2 recurrence + output
// ---------------------------------------------------------------------------

#define N_BATCH 128
#define T_SEQ   156
#define C_IN    156
#define H_DIM   1024
#define O_DIM   20
#define HB_CNT  8
#define HB_SZ   128
#define IDX_CAP 160
#define ROW_BYTES 512                 // ws row stride (128 floats)
#define ZROW_OFF ((unsigned)(C_IN * ROW_BYTES))
#define NGRP    8                     // n per fused block (8 warps)

#define LAM_S  0.90483741803595952f
#define K_PSP  0.27182818284590452f
#define LAM_R  0.36787944117144233f
#define C_REF  -54.365636569180902f
#define C_P16  1.1253517471925912e-07f
#define C_Q16  1.8005627955081459e-06f
#define THETA  10.0f

__device__ __constant__ int c_td[39] = {
    11,25,35,4,18,30,7,2,20,37,29,12,9,33,23,16,1,6,15,21,
    27,34,39,24,17,10,31,38,28,14,3,22,32,8,19,36,5,13,26};

#define NSLAB (2 * N_BATCH * HB_CNT)          // 2048 (path,n,hb) slabs
__device__ unsigned g_idx[(size_t)2 * N_BATCH * T_SEQ * IDX_CAP];   // 25.6MB
__device__ int      g_cnt[2 * N_BATCH * T_SEQ];
__device__ float    g_w1t[2][C_IN * H_DIM];                         // 1.3MB
__device__ unsigned g_sb[(size_t)NSLAB * T_SEQ * 4];                // 5.1MB

#define LDSV2(a, b, addr) \
    asm volatile("ld.shared.v2.b64 {%0,%1}, [%2];" : "=l"(a), "=l"(b) : "r"(addr))
#define FADD2(acc, x) \
    asm("add.rn.f32x2 %0, %0, %1;" : "+l"(acc) : "l"(x))

// ---------------------------------------------------------------------------
// K-1: transpose layer-1 weights: g_w1t[path][c*1024 + h] = w[h*156 + c].
// ---------------------------------------------------------------------------
__global__ void __launch_bounds__(256) k_wt(const float* __restrict__ w_main,
                                            const float* __restrict__ w_loc) {
    int i = blockIdx.x * 256 + threadIdx.x;
    if (i >= 2 * C_IN * H_DIM) return;
    int path = i / (C_IN * H_DIM);
    int r = i % (C_IN * H_DIM);
    int c = r / H_DIM, h = r % H_DIM;
    const float* w = path ? w_loc : w_main;
    g_w1t[path][r] = w[(size_t)h * C_IN + c];
}

// ---------------------------------------------------------------------------
// K0: ballot-compacted active-index lists (premultiplied byte offsets).
// ---------------------------------------------------------------------------
__global__ void __launch_bounds__(256) k_bitify(const float* __restrict__ x) {
    extern __shared__ float xs[];                 // [C_IN][T_SEQ]
    int n = blockIdx.x;
    const float* xb = x + (size_t)n * C_IN * T_SEQ;
    for (int i = threadIdx.x; i < C_IN * T_SEQ; i += blockDim.x) xs[i] = xb[i];
    __syncthreads();

    int wrp = threadIdx.x >> 5, lane = threadIdx.x & 31;
    for (int task = wrp; task < 2 * T_SEQ; task += 8) {
        int path = task >= T_SEQ;
        int seq = path ? task - T_SEQ : task;
        unsigned* ob = g_idx + ((size_t)(path * N_BATCH + n) * T_SEQ + seq) * IDX_CAP;

        int pc = 0;
        if (path) {
            int blk = seq / 78, j2 = seq % 78;
            pc = 2 * c_td[j2 >> 1] - 2 + (j2 & 1) + blk * 78;   // PERM[seq]
        }
        int total = 0;
        #pragma unroll
        for (int w = 0; w < 5; w++) {
            int j = w * 32 + lane;
            bool bit = false;
            if (j < C_IN)
                bit = (path ? xs[pc * T_SEQ + j] : xs[j * T_SEQ + seq]) > 0.5f;
            unsigned m = __ballot_sync(0xffffffffu, bit);
            int pos = total + __popc(m & ((1u << lane) - 1u));
            if (bit) ob[pos] = (unsigned)(j * ROW_BYTES);
            total += __popc(m);
        }
        if (lane == 0) {
            while (total & 3) ob[total++] = ZROW_OFF;
            g_cnt[(path * N_BATCH + n) * T_SEQ + seq] = total;
        }
    }
}

// ---------------------------------------------------------------------------
// K1: fused layer-1. grid (hb, N/8, path) = 256 blocks, 256 threads = 8 warps.
// Warp w handles n = ng*8+w for the block's hb. Lane owns h = hb*128 +
// lane*4 + {0..3}. No __syncthreads after weight load; each warp runs the
// full serial t-loop: matvec (frozen R8 order) -> recurrence -> spike pack.
// Spike words are canonical (bit j of word wd == h = wd*32+j), so k_final's
// frozen ascending-h traversal is preserved exactly.
// ---------------------------------------------------------------------------
__global__ void __launch_bounds__(256, 2) k_fused() {
    extern __shared__ float ws[];   // [157][128]; row 156 = zeros
    int hb = blockIdx.x, ng = blockIdx.y, path = blockIdx.z;
    int tid = threadIdx.x;

    const float* wt = g_w1t[path] + hb * HB_SZ;
    for (int i = tid; i < C_IN * HB_SZ; i += 256) {
        int c = i >> 7, hl = i & 127;
        ws[i] = wt[c * H_DIM + hl];
    }
    for (int i = tid; i < HB_SZ; i += 256) ws[C_IN * HB_SZ + i] = 0.0f;
    __syncthreads();

    uint32_t ws32;
    asm("{ .reg .u64 t; cvta.to.shared.u64 t, %1; cvt.u32.u64 %0, t; }"
        : "=r"(ws32) : "l"(ws));

    int wrp = tid >> 5, lane = tid & 31;
    uint32_t base = ws32 + lane * 16;
    int n = ng * NGRP + wrp;
    const int seqbase = (path * N_BATCH + n) * T_SEQ;
    int slab = (path * N_BATCH + n) * HB_CNT + hb;
    unsigned* sbout = g_sb + (size_t)slab * (T_SEQ * 4);

    float A[4] = {0.f, 0.f, 0.f, 0.f};
    float B[4] = {0.f, 0.f, 0.f, 0.f};
    float P[4] = {0.f, 0.f, 0.f, 0.f};
    float Q[4] = {0.f, 0.f, 0.f, 0.f};
    unsigned hist[4] = {0u, 0u, 0u, 0u};

    for (int t = 0; t < T_SEQ; t++) {
        // ---- sparse matvec (bit-exact R8 inner loop) ----
        const unsigned* ib = g_idx + (size_t)(seqbase + t) * IDX_CAP;
        int cnt = g_cnt[seqbase + t];
        unsigned long long acc0 = 0ULL, acc1 = 0ULL;
        for (int k = 0; k < cnt; k += 4) {
            uint4 v = *(const uint4*)(ib + k);
            unsigned long long a, b;
            LDSV2(a, b, base + v.x); FADD2(acc0, a); FADD2(acc1, b);
            LDSV2(a, b, base + v.y); FADD2(acc0, a); FADD2(acc1, b);
            LDSV2(a, b, base + v.z); FADD2(acc0, a); FADD2(acc1, b);
            LDSV2(a, b, base + v.w); FADD2(acc0, a); FADD2(acc1, b);
        }
        float pre[4];
        uint2 u0 = *reinterpret_cast<uint2*>(&acc0);
        uint2 u1 = *reinterpret_cast<uint2*>(&acc1);
        pre[0] = __uint_as_float(u0.x); pre[1] = __uint_as_float(u0.y);
        pre[2] = __uint_as_float(u1.x); pre[3] = __uint_as_float(u1.y);

        // ---- recurrence for 4 neurons (identical expressions to R8) ----
        unsigned nib = 0u;
        #pragma unroll
        for (int i = 0; i < 4; i++) {
            B[i] = LAM_S * (B[i] + A[i]);
            A[i] = LAM_S * A[i] + pre[i];
            float u  = K_PSP * B[i];
            float um = u + C_REF * Q[i];
            unsigned spk = (um >= THETA) ? 1u : 0u;
            float s = (float)spk;
            float aged = (float)((hist[i] >> 14) & 1u);
            Q[i] = LAM_R * (Q[i] + P[i] + s) - aged * C_Q16;
            P[i] = LAM_R * (P[i] + s)       - aged * C_P16;
            hist[i] = (hist[i] << 1) | spk;
            nib |= spk << i;
        }

        // ---- pack to canonical 32-bit words (bit j of word wd = h wd*32+j)
        unsigned v1 = nib | (__shfl_down_sync(0xffffffffu, nib, 1) << 4);
        unsigned v2 = v1  | (__shfl_down_sync(0xffffffffu, v1, 2) << 8);
        unsigned v3 = v2  | (__shfl_down_sync(0xffffffffu, v2, 4) << 16);
        if ((lane & 7) == 0) sbout[t * 4 + (lane >> 3)] = v3;
    }
}

// ---------------------------------------------------------------------------
// K2: s1 x W2 from bitmasks (per-hb partials summed in ascending hb order),
// then layer-2 recurrence + output. grid 256 = (path, n), 256 threads.
// ---------------------------------------------------------------------------
#define TO (T_SEQ * O_DIM)   // 3120
__global__ void __launch_bounds__(256) k_final(float* __restrict__ out,
                                               const float* __restrict__ wb_main,
                                               const float* __restrict__ wb_loc) {
    extern __shared__ float smem[];
    float* w2s = smem;                   // [1024][20], 80KB
    float* v   = smem + H_DIM * O_DIM;   // [156][20]

    int b = blockIdx.x;
    int path = b >> 7, n = b & 127;
    int tid = threadIdx.x;
    const float* wb = path ? wb_loc : wb_main;

    for (int i = tid; i < H_DIM * O_DIM; i += 256) {
        int o = i / H_DIM, h = i % H_DIM;
        w2s[h * O_DIM + o] = wb[(size_t)o * H_DIM + h];
    }
    __syncthreads();

    uint32_t w2s32;
    asm("{ .reg .u64 t; cvta.to.shared.u64 t, %1; cvt.u32.u64 %0, t; }"
        : "=r"(w2s32) : "l"(w2s));

    const unsigned* sbb = g_sb + (size_t)(path * N_BATCH + n) * HB_CNT * (T_SEQ * 4);

    for (int t = tid; t < T_SEQ; t += 256) {
        unsigned long long acc[10];
        #pragma unroll
        for (int i = 0; i < 10; i++) acc[i] = 0ULL;
        for (int hb = 0; hb < HB_CNT; hb++) {
            unsigned long long tmp[10];
            #pragma unroll
            for (int i = 0; i < 10; i++) tmp[i] = 0ULL;
            const unsigned* sm = sbb + (size_t)hb * (T_SEQ * 4) + t * 4;
            uint32_t hbbase = w2s32 + (unsigned)(hb * HB_SZ * O_DIM * 4);
            #pragma unroll
            for (int wd = 0; wd < 4; wd++) {
                unsigned m = sm[wd];
                while (m) {
                    int j = __ffs(m) - 1;
                    m &= m - 1u;
                    uint32_t row = hbbase + (unsigned)((wd * 32 + j) * (O_DIM * 4));
                    unsigned long long a, c;
                    LDSV2(a, c, row);
                    FADD2(tmp[0], a); FADD2(tmp[1], c);
                    LDSV2(a, c, row + 16);
                    FADD2(tmp[2], a); FADD2(tmp[3], c);
                    LDSV2(a, c, row + 32);
                    FADD2(tmp[4], a); FADD2(tmp[5], c);
                    LDSV2(a, c, row + 48);
                    FADD2(tmp[6], a); FADD2(tmp[7], c);
                    LDSV2(a, c, row + 64);
                    FADD2(tmp[8], a); FADD2(tmp[9], c);
                }
            }
            #pragma unroll
            for (int i = 0; i < 10; i++) FADD2(acc[i], tmp[i]);
        }
        float2* vp = (float2*)(v + t * O_DIM);
        #pragma unroll
        for (int i = 0; i < 10; i++) vp[i] = *reinterpret_cast<float2*>(&acc[i]);
    }
    __syncthreads();

    if (tid < O_DIM) {
        int o = tid;
        float* op = out + ((size_t)n * O_DIM + o) * 312 + path * T_SEQ;
        float A = 0.f, B = 0.f, P = 0.f, Q = 0.f;
        unsigned hist = 0u;
        #pragma unroll 4
        for (int t = 0; t < T_SEQ; t++) {
            float pre = v[t * O_DIM + o];
            B = LAM_S * (B + A);
            A = LAM_S * A + pre;
            float u  = K_PSP * B;
            float um = u + C_REF * Q;
            unsigned spk = (um >= THETA) ? 1u : 0u;
            float s = (float)spk;
            float aged = (float)((hist >> 14) & 1u);
            Q = LAM_R * (Q + P + s) - aged * C_Q16;
            P = LAM_R * (P + s)     - aged * C_P16;
            hist = (hist << 1) | spk;
            op[t] = s;
        }
    }
}

// ---------------------------------------------------------------------------
extern "C" void kernel_launch(void* const* d_in, const int* in_sizes, int n_in,
                              void* d_out, int out_size) {
    const float* x   = (const float*)d_in[0];
    const float* w1  = (const float*)d_in[1];
    const float* w2  = (const float*)d_in[2];
    const float* wl1 = (const float*)d_in[3];
    const float* wl2 = (const float*)d_in[4];
    float* out = (float*)d_out;

    const int SM0 = C_IN * T_SEQ * 4;                    // 97344
    const int SM1 = 157 * HB_SZ * 4;                     // 80384
    const int SM2 = (H_DIM * O_DIM + TO) * 4;            // 94400
    cudaFuncSetAttribute(k_bitify, cudaFuncAttributeMaxDynamicSharedMemorySize, SM0);
    cudaFuncSetAttribute(k_fused,  cudaFuncAttributeMaxDynamicSharedMemorySize, SM1);
    cudaFuncSetAttribute(k_final,  cudaFuncAttributeMaxDynamicSharedMemorySize, SM2);

    k_wt<<<(2 * C_IN * H_DIM + 255) / 256, 256>>>(w1, wl1);
    k_bitify<<<N_BATCH, 256, SM0>>>(x);

    dim3 gf(HB_CNT, N_BATCH / NGRP, 2);   // 256 blocks, 8 warps each
    k_fused<<<gf, 256, SM1>>>();

    k_final<<<2 * N_BATCH, 256, SM2>>>(out, w2, wl2);
}

// round 16
// speedup vs baseline: 1.4332x; 1.0071x over previous
#include <cuda_runtime.h>
#include <cstdint>

// ---------------------------------------------------------------------------
// LocationSlayerArch, round 16: R15 warp-fused layer 1 + cp.async idx
// double-buffering (hides the 234-cyc uniform idx LDG latency; bit-exact),
// and o-split k_final (2x thread utilization; o's independent so order is
// untouched).
// ---------------------------------------------------------------------------

#define N_BATCH 128
#define T_SEQ   156
#define C_IN    156
#define H_DIM   1024
#define O_DIM   20
#define HB_CNT  8
#define HB_SZ   128
#define IDX_CAP 160
#define ROW_BYTES 512                 // ws row stride (128 floats)
#define ZROW_OFF ((unsigned)(C_IN * ROW_BYTES))
#define NGRP    8                     // n per fused block (8 warps)
#define WS_FLT  (157 * 128)           // weight tile floats
#define WS_BYTES (WS_FLT * 4)         // 80384

#define LAM_S  0.90483741803595952f
#define K_PSP  0.27182818284590452f
#define LAM_R  0.36787944117144233f
#define C_REF  -54.365636569180902f
#define C_P16  1.1253517471925912e-07f
#define C_Q16  1.8005627955081459e-06f
#define THETA  10.0f

__device__ __constant__ int c_td[39] = {
    11,25,35,4,18,30,7,2,20,37,29,12,9,33,23,16,1,6,15,21,
    27,34,39,24,17,10,31,38,28,14,3,22,32,8,19,36,5,13,26};

#define NSLAB (2 * N_BATCH * HB_CNT)          // 2048 (path,n,hb) slabs
__device__ unsigned g_idx[(size_t)2 * N_BATCH * T_SEQ * IDX_CAP];   // 25.6MB
__device__ int      g_cnt[2 * N_BATCH * T_SEQ];
__device__ float    g_w1t[2][C_IN * H_DIM];                         // 1.3MB
__device__ unsigned g_sb[(size_t)NSLAB * T_SEQ * 4];                // 5.1MB

#define LDSV2(a, b, addr) \
    asm volatile("ld.shared.v2.b64 {%0,%1}, [%2];" : "=l"(a), "=l"(b) : "r"(addr))
#define LDS64(a, addr) \
    asm volatile("ld.shared.b64 %0, [%1];" : "=l"(a) : "r"(addr))
#define FADD2(acc, x) \
    asm("add.rn.f32x2 %0, %0, %1;" : "+l"(acc) : "l"(x))
#define LDSV4U(v, addr) \
    asm volatile("ld.shared.v4.u32 {%0,%1,%2,%3}, [%4];" \
                 : "=r"(v.x), "=r"(v.y), "=r"(v.z), "=r"(v.w) : "r"(addr))
#define CPASYNC16(dst, src) \
    asm volatile("cp.async.cg.shared.global [%0], [%1], 16;" :: "r"(dst), "l"(src))

// ---------------------------------------------------------------------------
// K-1: transpose layer-1 weights: g_w1t[path][c*1024 + h] = w[h*156 + c].
// ---------------------------------------------------------------------------
__global__ void __launch_bounds__(256) k_wt(const float* __restrict__ w_main,
                                            const float* __restrict__ w_loc) {
    int i = blockIdx.x * 256 + threadIdx.x;
    if (i >= 2 * C_IN * H_DIM) return;
    int path = i / (C_IN * H_DIM);
    int r = i % (C_IN * H_DIM);
    int c = r / H_DIM, h = r % H_DIM;
    const float* w = path ? w_loc : w_main;
    g_w1t[path][r] = w[(size_t)h * C_IN + c];
}

// ---------------------------------------------------------------------------
// K0: ballot-compacted active-index lists (premultiplied byte offsets).
// ---------------------------------------------------------------------------
__global__ void __launch_bounds__(256) k_bitify(const float* __restrict__ x) {
    extern __shared__ float xs[];                 // [C_IN][T_SEQ]
    int n = blockIdx.x;
    const float* xb = x + (size_t)n * C_IN * T_SEQ;
    for (int i = threadIdx.x; i < C_IN * T_SEQ; i += blockDim.x) xs[i] = xb[i];
    __syncthreads();

    int wrp = threadIdx.x >> 5, lane = threadIdx.x & 31;
    for (int task = wrp; task < 2 * T_SEQ; task += 8) {
        int path = task >= T_SEQ;
        int seq = path ? task - T_SEQ : task;
        unsigned* ob = g_idx + ((size_t)(path * N_BATCH + n) * T_SEQ + seq) * IDX_CAP;

        int pc = 0;
        if (path) {
            int blk = seq / 78, j2 = seq % 78;
            pc = 2 * c_td[j2 >> 1] - 2 + (j2 & 1) + blk * 78;   // PERM[seq]
        }
        int total = 0;
        #pragma unroll
        for (int w = 0; w < 5; w++) {
            int j = w * 32 + lane;
            bool bit = false;
            if (j < C_IN)
                bit = (path ? xs[pc * T_SEQ + j] : xs[j * T_SEQ + seq]) > 0.5f;
            unsigned m = __ballot_sync(0xffffffffu, bit);
            int pos = total + __popc(m & ((1u << lane) - 1u));
            if (bit) ob[pos] = (unsigned)(j * ROW_BYTES);
            total += __popc(m);
        }
        if (lane == 0) {
            while (total & 3) ob[total++] = ZROW_OFF;
            g_cnt[(path * N_BATCH + n) * T_SEQ + seq] = total;
        }
    }
}

// ---------------------------------------------------------------------------
// K1: fused layer-1 (R15) + cp.async idx double-buffering.
// grid (hb, N/8, path) = 256 blocks, 256 threads = 8 warps (one n each).
// Lane owns h = hb*128 + lane*4 + {0..3}. Per-warp 2x256B idx slots; list
// for t+1 prefetched while t is processed. Arithmetic identical to R15.
// ---------------------------------------------------------------------------
__global__ void __launch_bounds__(256, 2) k_fused() {
    extern __shared__ float ws[];   // [157][128] weights + idx slots
    int hb = blockIdx.x, ng = blockIdx.y, path = blockIdx.z;
    int tid = threadIdx.x;

    const float* wt = g_w1t[path] + hb * HB_SZ;
    for (int i = tid; i < C_IN * HB_SZ; i += 256) {
        int c = i >> 7, hl = i & 127;
        ws[i] = wt[c * H_DIM + hl];
    }
    for (int i = tid; i < HB_SZ; i += 256) ws[C_IN * HB_SZ + i] = 0.0f;
    __syncthreads();

    uint32_t ws32;
    asm("{ .reg .u64 t; cvta.to.shared.u64 t, %1; cvt.u32.u64 %0, t; }"
        : "=r"(ws32) : "l"(ws));

    int wrp = tid >> 5, lane = tid & 31;
    uint32_t base = ws32 + lane * 16;
    uint32_t slot0 = ws32 + WS_BYTES + wrp * 512;   // two 256B buffers
    int n = ng * NGRP + wrp;
    const int seqbase = (path * N_BATCH + n) * T_SEQ;
    int slab = (path * N_BATCH + n) * HB_CNT + hb;
    unsigned* sbout = g_sb + (size_t)slab * (T_SEQ * 4);

    float A[4] = {0.f, 0.f, 0.f, 0.f};
    float B[4] = {0.f, 0.f, 0.f, 0.f};
    float P[4] = {0.f, 0.f, 0.f, 0.f};
    float Q[4] = {0.f, 0.f, 0.f, 0.f};
    unsigned hist[4] = {0u, 0u, 0u, 0u};

    // prologue: stage list for t=0
    {
        const char* src = (const char*)(g_idx + (size_t)seqbase * IDX_CAP);
        if (lane < 16) CPASYNC16(slot0 + lane * 16, src + lane * 16);
        asm volatile("cp.async.commit_group;");
    }
    int cnt_cur = g_cnt[seqbase];

    for (int t = 0; t < T_SEQ; t++) {
        int cnt = cnt_cur;
        const unsigned* ib = g_idx + (size_t)(seqbase + t) * IDX_CAP;
        // prefetch t+1 while t is pending/processed
        if (t + 1 < T_SEQ) {
            const char* src = (const char*)(g_idx + (size_t)(seqbase + t + 1) * IDX_CAP);
            if (lane < 16)
                CPASYNC16(slot0 + (((t + 1) & 1) << 8) + lane * 16, src + lane * 16);
            asm volatile("cp.async.commit_group;");
            cnt_cur = g_cnt[seqbase + t + 1];
            asm volatile("cp.async.wait_group 1;" ::: "memory");
        } else {
            asm volatile("cp.async.wait_group 0;" ::: "memory");
        }
        __syncwarp();

        // ---- sparse matvec from staged smem idx (frozen R8/R15 order) ----
        uint32_t sl = slot0 + ((t & 1) << 8);
        unsigned long long acc0 = 0ULL, acc1 = 0ULL;
        int klim = cnt < 64 ? cnt : 64;
        int k = 0;
        for (; k < klim; k += 4) {
            uint4 v;
            LDSV4U(v, sl + (k << 2));
            unsigned long long a, b;
            LDSV2(a, b, base + v.x); FADD2(acc0, a); FADD2(acc1, b);
            LDSV2(a, b, base + v.y); FADD2(acc0, a); FADD2(acc1, b);
            LDSV2(a, b, base + v.z); FADD2(acc0, a); FADD2(acc1, b);
            LDSV2(a, b, base + v.w); FADD2(acc0, a); FADD2(acc1, b);
        }
        for (; k < cnt; k += 4) {                    // rare fallback (cnt>64)
            uint4 v = *(const uint4*)(ib + k);
            unsigned long long a, b;
            LDSV2(a, b, base + v.x); FADD2(acc0, a); FADD2(acc1, b);
            LDSV2(a, b, base + v.y); FADD2(acc0, a); FADD2(acc1, b);
            LDSV2(a, b, base + v.z); FADD2(acc0, a); FADD2(acc1, b);
            LDSV2(a, b, base + v.w); FADD2(acc0, a); FADD2(acc1, b);
        }
        float pre[4];
        uint2 u0 = *reinterpret_cast<uint2*>(&acc0);
        uint2 u1 = *reinterpret_cast<uint2*>(&acc1);
        pre[0] = __uint_as_float(u0.x); pre[1] = __uint_as_float(u0.y);
        pre[2] = __uint_as_float(u1.x); pre[3] = __uint_as_float(u1.y);

        // ---- recurrence for 4 neurons (identical expressions) ----
        unsigned nib = 0u;
        #pragma unroll
        for (int i = 0; i < 4; i++) {
            B[i] = LAM_S * (B[i] + A[i]);
            A[i] = LAM_S * A[i] + pre[i];
            float u  = K_PSP * B[i];
            float um = u + C_REF * Q[i];
            unsigned spk = (um >= THETA) ? 1u : 0u;
            float s = (float)spk;
            float aged = (float)((hist[i] >> 14) & 1u);
            Q[i] = LAM_R * (Q[i] + P[i] + s) - aged * C_Q16;
            P[i] = LAM_R * (P[i] + s)       - aged * C_P16;
            hist[i] = (hist[i] << 1) | spk;
            nib |= spk << i;
        }

        // ---- pack to canonical 32-bit words ----
        unsigned v1 = nib | (__shfl_down_sync(0xffffffffu, nib, 1) << 4);
        unsigned v2 = v1  | (__shfl_down_sync(0xffffffffu, v1, 2) << 8);
        unsigned v3 = v2  | (__shfl_down_sync(0xffffffffu, v2, 4) << 16);
        if ((lane & 7) == 0) sbout[t * 4 + (lane >> 3)] = v3;
    }
}

// ---------------------------------------------------------------------------
// K2: s1 x W2 from bitmasks + layer-2 recurrence + output.
// grid 256 = (path, n), 256 threads. Task = (t, o-half): 312 tasks.
// o's are independent accumulators -> splitting o preserves all sum orders.
// ---------------------------------------------------------------------------
#define TO (T_SEQ * O_DIM)   // 3120
__global__ void __launch_bounds__(256) k_final(float* __restrict__ out,
                                               const float* __restrict__ wb_main,
                                               const float* __restrict__ wb_loc) {
    extern __shared__ float smem[];
    float* w2s = smem;                   // [1024][20], 80KB
    float* v   = smem + H_DIM * O_DIM;   // [156][20]

    int b = blockIdx.x;
    int path = b >> 7, n = b & 127;
    int tid = threadIdx.x;
    const float* wb = path ? wb_loc : wb_main;

    for (int i = tid; i < H_DIM * O_DIM; i += 256) {
        int o = i / H_DIM, h = i % H_DIM;
        w2s[h * O_DIM + o] = wb[(size_t)o * H_DIM + h];
    }
    __syncthreads();

    uint32_t w2s32;
    asm("{ .reg .u64 t; cvta.to.shared.u64 t, %1; cvt.u32.u64 %0, t; }"
        : "=r"(w2s32) : "l"(w2s));

    const unsigned* sbb = g_sb + (size_t)(path * N_BATCH + n) * HB_CNT * (T_SEQ * 4);

    for (int u = tid; u < 2 * T_SEQ; u += 256) {
        int t = u >> 1, oh = u & 1;           // o-half: o = oh*10 .. oh*10+9
        uint32_t obyte = (unsigned)(oh * 40);
        unsigned long long acc[5];
        #pragma unroll
        for (int i = 0; i < 5; i++) acc[i] = 0ULL;
        for (int hb = 0; hb < HB_CNT; hb++) {
            unsigned long long tmp[5];
            #pragma unroll
            for (int i = 0; i < 5; i++) tmp[i] = 0ULL;
            const unsigned* sm = sbb + (size_t)hb * (T_SEQ * 4) + t * 4;
            uint32_t hbbase = w2s32 + (unsigned)(hb * HB_SZ * O_DIM * 4) + obyte;
            #pragma unroll
            for (int wd = 0; wd < 4; wd++) {
                unsigned m = sm[wd];
                while (m) {
                    int j = __ffs(m) - 1;
                    m &= m - 1u;
                    uint32_t row = hbbase + (unsigned)((wd * 32 + j) * (O_DIM * 4));
                    unsigned long long a;
                    LDS64(a, row);      FADD2(tmp[0], a);
                    LDS64(a, row + 8);  FADD2(tmp[1], a);
                    LDS64(a, row + 16); FADD2(tmp[2], a);
                    LDS64(a, row + 24); FADD2(tmp[3], a);
                    LDS64(a, row + 32); FADD2(tmp[4], a);
                }
            }
            #pragma unroll
            for (int i = 0; i < 5; i++) FADD2(acc[i], tmp[i]);
        }
        float2* vp = (float2*)(v + t * O_DIM + oh * 10);
        #pragma unroll
        for (int i = 0; i < 5; i++) vp[i] = *reinterpret_cast<float2*>(&acc[i]);
    }
    __syncthreads();

    if (tid < O_DIM) {
        int o = tid;
        float* op = out + ((size_t)n * O_DIM + o) * 312 + path * T_SEQ;
        float A = 0.f, B = 0.f, P = 0.f, Q = 0.f;
        unsigned hist = 0u;
        #pragma unroll 4
        for (int t = 0; t < T_SEQ; t++) {
            float pre = v[t * O_DIM + o];
            B = LAM_S * (B + A);
            A = LAM_S * A + pre;
            float u  = K_PSP * B;
            float um = u + C_REF * Q;
            unsigned spk = (um >= THETA) ? 1u : 0u;
            float s = (float)spk;
            float aged = (float)((hist >> 14) & 1u);
            Q = LAM_R * (Q + P + s) - aged * C_Q16;
            P = LAM_R * (P + s)     - aged * C_P16;
            hist = (hist << 1) | spk;
            op[t] = s;
        }
    }
}

// ---------------------------------------------------------------------------
extern "C" void kernel_launch(void* const* d_in, const int* in_sizes, int n_in,
                              void* d_out, int out_size) {
    const float* x   = (const float*)d_in[0];
    const float* w1  = (const float*)d_in[1];
    const float* w2  = (const float*)d_in[2];
    const float* wl1 = (const float*)d_in[3];
    const float* wl2 = (const float*)d_in[4];
    float* out = (float*)d_out;

    const int SM0 = C_IN * T_SEQ * 4;                    // 97344
    const int SM1 = WS_BYTES + 8 * 512;                  // 84480
    const int SM2 = (H_DIM * O_DIM + TO) * 4;            // 94400
    cudaFuncSetAttribute(k_bitify, cudaFuncAttributeMaxDynamicSharedMemorySize, SM0);
    cudaFuncSetAttribute(k_fused,  cudaFuncAttributeMaxDynamicSharedMemorySize, SM1);
    cudaFuncSetAttribute(k_final,  cudaFuncAttributeMaxDynamicSharedMemorySize, SM2);

    k_wt<<<(2 * C_IN * H_DIM + 255) / 256, 256>>>(w1, wl1);
    k_bitify<<<N_BATCH, 256, SM0>>>(x);

    dim3 gf(HB_CNT, N_BATCH / NGRP, 2);   // 256 blocks, 8 warps each
    k_fused<<<gf, 256, SM1>>>();

    k_final<<<2 * N_BATCH, 256, SM2>>>(out, w2, wl2);
}